// round 15
// baseline (speedup 1.0000x reference)
#include <cuda_runtime.h>

#define ROWS 48
#define ROW_ELEMS (512 * 512)                  // 262144 elements per (b,c) row
#define CHUNKS 32
#define CHUNK_ELEMS (ROW_ELEMS / CHUNKS)       // 8192
#define THREADS 256
#define VEC_PER_THREAD (CHUNK_ELEMS / 4 / THREADS)  // 8 float4 per thread

// Per-(row,chunk) partial min/max. Every slot is written unconditionally by
// minmax_kernel on every call -> no init kernel, no atomics, deterministic.
__device__ float g_pmin[ROWS][CHUNKS];
__device__ float g_pmax[ROWS][CHUNKS];

__global__ void __launch_bounds__(THREADS) minmax_kernel(const float4* __restrict__ in) {
    const int row = blockIdx.y;
    const int chunk = blockIdx.x;
    const long base4 = (long)row * (ROW_ELEMS / 4) + (long)chunk * (CHUNK_ELEMS / 4);
    const int tid = threadIdx.x;

    float mn = 3.402823466e+38f;
    float mx = -3.402823466e+38f;

#pragma unroll
    for (int k = 0; k < VEC_PER_THREAD; k++) {
        float4 v = in[base4 + k * THREADS + tid];
        mn = fminf(mn, fminf(fminf(v.x, v.y), fminf(v.z, v.w)));
        mx = fmaxf(mx, fmaxf(fmaxf(v.x, v.y), fmaxf(v.z, v.w)));
    }

#pragma unroll
    for (int o = 16; o > 0; o >>= 1) {
        mn = fminf(mn, __shfl_xor_sync(0xffffffffu, mn, o));
        mx = fmaxf(mx, __shfl_xor_sync(0xffffffffu, mx, o));
    }

    __shared__ float smn[THREADS / 32];
    __shared__ float smx[THREADS / 32];
    if ((tid & 31) == 0) {
        smn[tid >> 5] = mn;
        smx[tid >> 5] = mx;
    }
    __syncthreads();

    if (tid == 0) {
        float bmn = smn[0], bmx = smx[0];
#pragma unroll
        for (int w = 1; w < THREADS / 32; w++) {
            bmn = fminf(bmn, smn[w]);
            bmx = fmaxf(bmx, smx[w]);
        }
        g_pmin[row][chunk] = bmn;
        g_pmax[row][chunk] = bmx;
    }
}

// Reference-exact bound: b_j = fl32( mn + fl32( d * (j/16) ) ), j/16 exact.
// Exact-rounding intrinsics block fma contraction (must match JAX bit-for-bit).
__device__ __forceinline__ float bound_j(float mn, float d, int j) {
    return __fadd_rn(mn, __fmul_rn(d, (float)j * 0.0625f));
}
// Reference-exact mid: m_j = fl32( 0.5 * fl32( b_j + b_{j+1} ) ).
__device__ __forceinline__ float mid_j(float mn, float d, int j) {
    return __fmul_rn(0.5f, __fadd_rn(bound_j(mn, d, j), bound_j(mn, d, j + 1)));
}

__global__ void __launch_bounds__(THREADS) quantize_kernel(const float4* __restrict__ in,
                                                           float4* __restrict__ out) {
    const int row = blockIdx.y;
    const int chunk = blockIdx.x;
    const long base4 = (long)row * (ROW_ELEMS / 4) + (long)chunk * (CHUNK_ELEMS / 4);
    const int tid = threadIdx.x;
    const int lane = tid & 31;

    // One warp reduces the 32 partials; broadcast via 2 smem floats.
    __shared__ float s_mn, s_mx;
    if (tid < 32) {
        float v1 = g_pmin[row][tid];
        float v2 = g_pmax[row][tid];
#pragma unroll
        for (int o = 16; o > 0; o >>= 1) {
            v1 = fminf(v1, __shfl_xor_sync(0xffffffffu, v1, o));
            v2 = fmaxf(v2, __shfl_xor_sync(0xffffffffu, v2, o));
        }
        if (tid == 0) { s_mn = v1; s_mx = v2; }
    }
    __syncthreads();

    const float mn = s_mn;
    const float mx = s_mx;
    const float d = __fadd_rn(mx, -mn);  // mx >= mn

    // Degenerate test, matching float32 reference arithmetic:
    // robust_eps = 4 * FLT_EPSILON; deg = d <= robust_eps + 1e-5 * |mx|
    const float thresh = __fadd_rn(4.76837158203125e-07f, __fmul_rn(1e-5f, fabsf(mx)));
    if (d <= thresh) {
        float4 q;
        q.x = q.y = q.z = q.w = mn;
#pragma unroll
        for (int k = 0; k < VEC_PER_THREAD; k++) {
            out[base4 + k * THREADS + tid] = q;
        }
        return;
    }

    // Warp-register mid table: lane L holds m_L (L<=15; clamped above).
    // The PROBE is computed arithmetically (FMA pipe is idle) instead of
    // shuffled: b_idx = fadd(mn, fmul(d, idxf*0.0625)) is bit-identical to
    // the table bound because idxf is an integer <= 16, so idxf*0.0625 is
    // exact. Only ONE shuffle (the mid lookup) remains per element.
    const float m_lane = mid_j(mn, d, (lane <= 15) ? lane : 15);

    const float scale = 16.0f / d;
    const float bias = __fmaf_rn(-mn, scale, 0.5f);  // (x-mn)*scale + 0.5, one FFMA

#pragma unroll
    for (int k = 0; k < VEC_PER_THREAD; k++) {
        float4 v = in[base4 + k * THREADS + tid];
        float xv[4] = {v.x, v.y, v.z, v.w};
        float qv[4];
#pragma unroll
        for (int e = 0; e < 4; e++) {
            float x = xv[e];
            // idx = floor((x-mn)*scale + 0.5) clamped to [0,16]; provably in
            // {r_true, r_true+1} (same estimate as rounds 8/13, rel_err=0).
            float idxf = fminf(fmaxf(floorf(__fmaf_rn(x, scale, bias)), 0.0f), 16.0f);
            int idx = __float2int_rz(idxf);
            // Exact probe, no shuffle: b_idx = fl(mn + fl(d * (idx/16))).
            float probe = __fadd_rn(mn, __fmul_rn(d, __fmul_rn(idxf, 0.0625f)));
            // x >= b_idx -> region idx; x < b_idx -> region idx-1.
            // idx=0: probe=mn <= x always (no underflow). idx=16 with
            // x >= fl(mn+d) possible -> clamp to 15.
            int r = min(idx - ((x < probe) ? 1 : 0), 15);
            qv[e] = __shfl_sync(0xffffffffu, m_lane, r);
        }
        float4 q;
        q.x = qv[0]; q.y = qv[1]; q.z = qv[2]; q.w = qv[3];
        out[base4 + k * THREADS + tid] = q;
    }
}

extern "C" void kernel_launch(void* const* d_in, const int* in_sizes, int n_in,
                              void* d_out, int out_size) {
    const float4* in = (const float4*)d_in[0];
    float4* out = (float4*)d_out;

    dim3 grid(CHUNKS, ROWS);
    minmax_kernel<<<grid, THREADS>>>(in);
    quantize_kernel<<<grid, THREADS>>>(in, out);
}